// round 1
// baseline (speedup 1.0000x reference)
#include <cuda_runtime.h>
#include <cstdint>

#define M_Q   4096
#define N_B   65536
#define D     128
#define KNN   9
#define QPB   32          // queries per CTA
#define TILE_N 128        // bank vectors per smem tile
#define NSPLIT 2          // split of N across CTAs (grid.y)
#define NPART (N_B / NSPLIT)
#define THREADS 256
#define PART_STRIDE 12    // padded stride for partial top-9 lists

// Scratch (device globals — no allocation allowed)
__device__ float g_bsq[N_B];
__device__ float g_qsq[M_Q];
__device__ float g_part[NSPLIT * M_Q * PART_STRIDE];

// ---------------------------------------------------------------------------
// packed f32x2 FMA (Blackwell dual fp32 path; ptxas never emits it from C++)
// ---------------------------------------------------------------------------
union F2U { float2 f; unsigned long long u; };

__device__ __forceinline__ float2 ffma2(float2 a, float2 b, float2 c) {
    F2U A, B, C, R;
    A.f = a; B.f = b; C.f = c;
    asm("fma.rn.f32x2 %0, %1, %2, %3;" : "=l"(R.u) : "l"(A.u), "l"(B.u), "l"(C.u));
    return R.f;
}

// ---------------------------------------------------------------------------
// Kernel 0: squared norms (one warp per vector, float4 loads, shfl reduce)
// ---------------------------------------------------------------------------
__global__ void norms_b_kernel(const float4* __restrict__ data) {
    int gw = (blockIdx.x * blockDim.x + threadIdx.x) >> 5;
    int lane = threadIdx.x & 31;
    if (gw >= N_B) return;
    float4 d = data[gw * 32 + lane];
    float s = d.x * d.x + d.y * d.y + d.z * d.z + d.w * d.w;
#pragma unroll
    for (int off = 16; off; off >>= 1) s += __shfl_xor_sync(0xffffffffu, s, off);
    if (lane == 0) g_bsq[gw] = s;
}

__global__ void norms_q_kernel(const float4* __restrict__ data) {
    int gw = (blockIdx.x * blockDim.x + threadIdx.x) >> 5;
    int lane = threadIdx.x & 31;
    if (gw >= M_Q) return;
    float4 d = data[gw * 32 + lane];
    float s = d.x * d.x + d.y * d.y + d.z * d.z + d.w * d.w;
#pragma unroll
    for (int off = 16; off; off >>= 1) s += __shfl_xor_sync(0xffffffffu, s, off);
    if (lane == 0) g_qsq[gw] = s;
}

// ---------------------------------------------------------------------------
// Main kernel: tiled distance GEMM + streaming per-thread top-9.
//   warp w  <-> queries 4w..4w+3   (q loads are warp-broadcast LDS.128)
//   lane c  <-> banks  c, c+32, c+64, c+96 within the 128-bank tile
//   b tile stored swizzled: float4 (b, k4) at column (k4 ^ (b & 31))
//     -> STS conflict-free, LDS conflict-free ((addr/16)%32 == k4^c distinct)
//   selection key s = |b|^2 - 2*dot   (|q|^2 folded in at finalize)
// ---------------------------------------------------------------------------
__global__ void __launch_bounds__(THREADS) knn_main_kernel(
    const float4* __restrict__ qf4, const float4* __restrict__ bf4)
{
    extern __shared__ float4 smem[];
    float4* b_s   = smem;                       // [TILE_N][32] swizzled
    float4* q_s   = smem + TILE_N * 32;         // [QPB][32]
    float*  bsq_s = (float*)(q_s + QPB * 32);   // [TILE_N]

    const int t = threadIdx.x;
    const int w = t >> 5;
    const int c = t & 31;
    const int qbase = blockIdx.x * QPB;
    const int nbeg  = blockIdx.y * NPART;
    const float INF = __int_as_float(0x7f800000);

    // load query tile once (coalesced)
    for (int i = t; i < QPB * 32; i += THREADS)
        q_s[i] = qf4[qbase * 32 + i];

    float heap[4][KNN];
    float thr[4];
#pragma unroll
    for (int qq = 0; qq < 4; qq++) {
        thr[qq] = INF;
#pragma unroll
        for (int i = 0; i < KNN; i++) heap[qq][i] = INF;
    }

    for (int tile = 0; tile < NPART; tile += TILE_N) {
        __syncthreads();
        // load bank tile, transposed-by-swizzle (coalesced LDG.128)
        for (int i = t; i < TILE_N * 32; i += THREADS) {
            int b  = i >> 5;
            int k4 = i & 31;
            b_s[b * 32 + (k4 ^ (b & 31))] = bf4[(size_t)(nbeg + tile + b) * 32 + k4];
        }
        if (t < TILE_N) bsq_s[t] = g_bsq[nbeg + tile + t];
        __syncthreads();

        float2 acc[4][4];
#pragma unroll
        for (int qq = 0; qq < 4; qq++)
#pragma unroll
            for (int j = 0; j < 4; j++) acc[qq][j] = make_float2(0.f, 0.f);

#pragma unroll 8
        for (int k4 = 0; k4 < 32; k4++) {
            const int col = k4 ^ c;   // (c+32j)&31 == c  -> same column for all j
            float4 bv[4];
#pragma unroll
            for (int j = 0; j < 4; j++) bv[j] = b_s[(c + 32 * j) * 32 + col];
#pragma unroll
            for (int qq = 0; qq < 4; qq++) {
                float4 qv = q_s[(4 * w + qq) * 32 + k4];  // warp-broadcast
                float2 qlo = make_float2(qv.x, qv.y);
                float2 qhi = make_float2(qv.z, qv.w);
#pragma unroll
                for (int j = 0; j < 4; j++) {
                    float2 blo = make_float2(bv[j].x, bv[j].y);
                    float2 bhi = make_float2(bv[j].z, bv[j].w);
                    acc[qq][j] = ffma2(qlo, blo, acc[qq][j]);
                    acc[qq][j] = ffma2(qhi, bhi, acc[qq][j]);
                }
            }
        }

        // epilogue: fold to scalar, streaming top-9 update
#pragma unroll
        for (int qq = 0; qq < 4; qq++) {
#pragma unroll
            for (int j = 0; j < 4; j++) {
                float dot = acc[qq][j].x + acc[qq][j].y;
                float s   = fmaf(-2.0f, dot, bsq_s[c + 32 * j]);
                if (s < thr[qq]) {
                    bool done = false;
#pragma unroll
                    for (int i = 0; i < KNN; i++) {
                        if (!done && heap[qq][i] == thr[qq]) { heap[qq][i] = s; done = true; }
                    }
                    float m = heap[qq][0];
#pragma unroll
                    for (int i = 1; i < KNN; i++) m = fmaxf(m, heap[qq][i]);
                    thr[qq] = m;
                }
            }
        }
    }

    // warp merge: 32 lanes x 9 values -> 9 global smallest per query
    const unsigned FULL = 0xffffffffu;
#pragma unroll 1
    for (int qq = 0; qq < 4; qq++) {
        int qglob = qbase + 4 * w + qq;
        float* dst = &g_part[((size_t)blockIdx.y * M_Q + qglob) * PART_STRIDE];
#pragma unroll 1
        for (int r = 0; r < KNN; r++) {
            float lm = heap[qq][0];
#pragma unroll
            for (int i = 1; i < KNN; i++) lm = fminf(lm, heap[qq][i]);
            float wm = lm;
#pragma unroll
            for (int off = 16; off; off >>= 1)
                wm = fminf(wm, __shfl_xor_sync(FULL, wm, off));
            unsigned mask = __ballot_sync(FULL, lm == wm);
            int src = __ffs(mask) - 1;
            if (c == src) {
                bool done = false;
#pragma unroll
                for (int i = 0; i < KNN; i++) {
                    if (!done && heap[qq][i] == wm) { heap[qq][i] = INF; done = true; }
                }
            }
            if (c == 0) dst[r] = wm;
        }
    }
}

// ---------------------------------------------------------------------------
// Finalize: merge NSPLIT partial top-9 lists, add |q|^2, sqrt, mean.
// Branch-free rank selection over 18 candidates (ties broken by index).
// ---------------------------------------------------------------------------
__global__ void knn_finalize_kernel(float* __restrict__ out) {
    int qi = blockIdx.x * blockDim.x + threadIdx.x;
    if (qi >= M_Q) return;
    float v[NSPLIT * KNN];
#pragma unroll
    for (int s = 0; s < NSPLIT; s++)
#pragma unroll
        for (int r = 0; r < KNN; r++)
            v[s * KNN + r] = g_part[((size_t)s * M_Q + qi) * PART_STRIDE + r];

    float qsq = g_qsq[qi];
    float sum = 0.0f;
#pragma unroll
    for (int i = 0; i < NSPLIT * KNN; i++) {
        int rank = 0;
#pragma unroll
        for (int j = 0; j < NSPLIT * KNN; j++)
            rank += (v[j] < v[i]) || (v[j] == v[i] && j < i);
        if (rank < KNN) sum += sqrtf(fmaxf(v[i] + qsq, 0.0f));
    }
    out[qi] = sum * (1.0f / KNN);
}

// ---------------------------------------------------------------------------
extern "C" void kernel_launch(void* const* d_in, const int* in_sizes, int n_in,
                              void* d_out, int out_size)
{
    const float4* q = (const float4*)d_in[0];   // features    [4096,128]
    const float4* b = (const float4*)d_in[1];   // memory_bank [65536,128]
    if (n_in >= 2 && in_sizes[0] > in_sizes[1]) {  // defensive: order by size
        const float4* tmp = q; q = b; b = tmp;
    }
    float* out = (float*)d_out;

    const int smem_bytes = (TILE_N * 32 + QPB * 32) * (int)sizeof(float4)
                         + TILE_N * (int)sizeof(float);   // 82432 B
    cudaFuncSetAttribute(knn_main_kernel,
                         cudaFuncAttributeMaxDynamicSharedMemorySize, smem_bytes);

    norms_b_kernel<<<N_B / 8, 256>>>(b);
    norms_q_kernel<<<M_Q / 8, 256>>>(q);

    dim3 grid(M_Q / QPB, NSPLIT);
    knn_main_kernel<<<grid, THREADS, smem_bytes>>>(q, b);

    knn_finalize_kernel<<<M_Q / 256, 256>>>(out);
}

// round 3
// speedup vs baseline: 1.9052x; 1.9052x over previous
#include <cuda_runtime.h>
#include <cuda_fp16.h>
#include <cstdint>

#define M_Q   4096
#define N_B   65536
#define D_DIM 128
#define KNN   9
#define MTILE 128
#define NTILE 128
#define NSPLIT 4
#define NPART (N_B / NSPLIT)          // 16384
#define T_TILES (NPART / NTILE)       // 128
#define THREADS 256
#define PART_STRIDE 12
#define NLISTS 16                     // 4 N-splits x 4 lanes-per-row

// ---------------------------------------------------------------------------
// Device-global scratch (no allocation allowed)
// ---------------------------------------------------------------------------
__device__ __align__(16) float g_bsq[N_B];
__device__ __align__(16) float g_qsq[M_Q];
__device__ __align__(16) float g_part[NLISTS * M_Q * PART_STRIDE];
__device__ __align__(16) __half g_bh[(size_t)N_B * D_DIM];
__device__ __align__(16) __half g_qh[(size_t)M_Q * D_DIM];

// ---------------------------------------------------------------------------
// SMEM layout: A tile 32KB, B tiles 2x32KB, bsq 2x512B   (dynamic smem)
// Tiles are [vec][dim] fp16, 256B rows, 16B-chunk XOR swizzle (ldmatrix-safe)
// ---------------------------------------------------------------------------
#define OFF_A    0
#define OFF_B    32768
#define OFF_BSQ  (32768 + 2 * 32768)    // 98304
#define SMEM_SZ  (OFF_BSQ + 2 * 512)    // 99328

// ---------------------------------------------------------------------------
// PTX helpers (all family-compatible: sm_80-level PTX only)
// ---------------------------------------------------------------------------
__device__ __forceinline__ uint32_t smem_u32(const void* p) {
    uint32_t a;
    asm("{ .reg .u64 t; cvta.to.shared.u64 t, %1; cvt.u32.u64 %0, t; }" : "=r"(a) : "l"(p));
    return a;
}
__device__ __forceinline__ void cp16(uint32_t dst, const void* src) {
    asm volatile("cp.async.cg.shared.global [%0], [%1], 16;" :: "r"(dst), "l"(src));
}
__device__ __forceinline__ void cp_commit() { asm volatile("cp.async.commit_group;" ::: "memory"); }
__device__ __forceinline__ void cp_wait1()  { asm volatile("cp.async.wait_group 1;" ::: "memory"); }

__device__ __forceinline__ void ldsm4(uint32_t* r, uint32_t addr) {
    asm volatile("ldmatrix.sync.aligned.m8n8.x4.shared.b16 {%0,%1,%2,%3}, [%4];"
                 : "=r"(r[0]), "=r"(r[1]), "=r"(r[2]), "=r"(r[3]) : "r"(addr));
}
__device__ __forceinline__ void mma16816(float* c, const uint32_t* a, const uint32_t* b) {
    asm volatile(
        "mma.sync.aligned.m16n8k16.row.col.f32.f16.f16.f32 "
        "{%0,%1,%2,%3}, {%4,%5,%6,%7}, {%8,%9}, {%0,%1,%2,%3};"
        : "+f"(c[0]), "+f"(c[1]), "+f"(c[2]), "+f"(c[3])
        : "r"(a[0]), "r"(a[1]), "r"(a[2]), "r"(a[3]), "r"(b[0]), "r"(b[1]));
}

// ---------------------------------------------------------------------------
// Pre-pass kernels
// ---------------------------------------------------------------------------
__global__ void to_half_kernel(const float4* __restrict__ src,
                               __half2* __restrict__ dst, int n4) {
    int i = blockIdx.x * blockDim.x + threadIdx.x;
    if (i >= n4) return;
    float4 v = src[i];
    dst[2 * i]     = __floats2half2_rn(v.x, v.y);
    dst[2 * i + 1] = __floats2half2_rn(v.z, v.w);
}

__global__ void norms_kernel(const float4* __restrict__ data, float* __restrict__ out, int nvec) {
    int gw = (blockIdx.x * blockDim.x + threadIdx.x) >> 5;
    int lane = threadIdx.x & 31;
    if (gw >= nvec) return;
    float4 d = data[gw * 32 + lane];
    float s = d.x * d.x + d.y * d.y + d.z * d.z + d.w * d.w;
#pragma unroll
    for (int off = 16; off; off >>= 1) s += __shfl_xor_sync(0xffffffffu, s, off);
    if (lane == 0) out[gw] = s;
}

// ---------------------------------------------------------------------------
// Streaming top-9 (registers only, fully unrolled)
// ---------------------------------------------------------------------------
__device__ __forceinline__ void top9_insert(float s, float (&heap)[KNN], float& thr) {
    if (s < thr) {
        bool done = false;
#pragma unroll
        for (int i = 0; i < KNN; i++)
            if (!done && heap[i] == thr) { heap[i] = s; done = true; }
        float m = heap[0];
#pragma unroll
        for (int i = 1; i < KNN; i++) m = fmaxf(m, heap[i]);
        thr = m;
    }
}

// load B tile (+ bsq) for tile index tt into buffer buf
__device__ __forceinline__ void issue_B_loads(uint32_t sm, int buf, int bank0,
                                              int tid, int slot) {
    const uint32_t dstb = sm + OFF_B + buf * 32768;
#pragma unroll
    for (int k = 0; k < 8; k++) {
        int i = tid + k * THREADS;
        int r = i >> 4, c = i & 15;
        uint32_t dst = dstb + r * 256 + ((c ^ (r & 7)) << 4);
        cp16(dst, g_bh + (size_t)(bank0 + r) * D_DIM + c * 8);
    }
    if (tid < 32)
        cp16(sm + OFF_BSQ + slot * 512 + tid * 16, g_bsq + bank0 + tid * 4);
}

// ---------------------------------------------------------------------------
// Main kernel: fp16 mma.sync distance GEMM + per-thread streaming top-9
// grid = (M_Q/128, NSPLIT), 256 threads (8 warps, warp w = rows w*16..w*16+15)
// ---------------------------------------------------------------------------
__global__ void __launch_bounds__(THREADS, 1) knn_main_kernel() {
    extern __shared__ char smem[];
    const uint32_t sm = smem_u32(smem);
    const int tid  = threadIdx.x;
    const int wid  = tid >> 5;
    const int lane = tid & 31;
    const int g    = lane >> 2;   // group (row within fragment)
    const int tig  = lane & 3;    // thread-in-group (col pairs)
    const int qbase = blockIdx.x * MTILE;
    const int nbeg  = blockIdx.y * NPART;
    const float INF = __int_as_float(0x7f800000);

    // ---- prologue: group0 = A tile + B tile0 + bsq0; group1 = B tile1 + bsq1
    {
        const uint32_t dsta = sm + OFF_A;
#pragma unroll
        for (int k = 0; k < 8; k++) {
            int i = tid + k * THREADS;
            int r = i >> 4, c = i & 15;
            uint32_t dst = dsta + r * 256 + ((c ^ (r & 7)) << 4);
            cp16(dst, g_qh + (size_t)(qbase + r) * D_DIM + c * 8);
        }
    }
    issue_B_loads(sm, 0, nbeg, tid, 0);
    cp_commit();
    issue_B_loads(sm, 1, nbeg + NTILE, tid, 1);
    cp_commit();

    // ---- wait group0 (A + B0), preload all A fragments into registers
    cp_wait1();
    __syncthreads();

    uint32_t aF[8][4];
    {
        const int m0 = wid * 16;
        const int rbase = lane & 15;
        const int shi = lane >> 4;
        const int rsw = rbase & 7;
        const uint32_t arow = sm + OFF_A + (m0 + rbase) * 256;
#pragma unroll
        for (int s = 0; s < 8; s++)
            ldsm4(aF[s], arow + (((2 * s + shi) ^ rsw) << 4));
    }

    float heap0[KNN], heap1[KNN];
    float thr0 = INF, thr1 = INF;
#pragma unroll
    for (int i = 0; i < KNN; i++) { heap0[i] = INF; heap1[i] = INF; }

    // per-lane invariants for B ldmatrix addressing
    const int rbaseB = (lane & 7) + ((lane >> 4) << 3);
    const int shiB   = (lane >> 3) & 1;
    const int rswB   = lane & 7;

#pragma unroll 1
    for (int t = 0; t < T_TILES; t++) {
        const int buf = t & 1;

        if (t > 0) {          // tile t loads complete (group t), t+1 pending
            cp_wait1();
            __syncthreads();
        }

        // ---- GEMM: 128x128x128 per CTA, warp = 16 rows x 128 cols
        float acc[16][4];
#pragma unroll
        for (int f = 0; f < 16; f++)
#pragma unroll
            for (int x = 0; x < 4; x++) acc[f][x] = 0.0f;

        const uint32_t Bb = sm + OFF_B + buf * 32768 + rbaseB * 256;
#pragma unroll
        for (int s = 0; s < 8; s++) {
            const uint32_t segoff = ((2 * s + shiB) ^ rswB) << 4;
#pragma unroll
            for (int j = 0; j < 8; j++) {
                uint32_t b[4];
                ldsm4(b, Bb + j * 4096 + segoff);
                mma16816(acc[2 * j],     aF[s], b);
                mma16816(acc[2 * j + 1], aF[s], b + 2);
            }
        }

        // ---- epilogue: key = bsq - 2*dot, streaming top-9 per thread-row
        {
            const float2* bq2 = (const float2*)(smem + OFF_BSQ + buf * 512);
#pragma unroll
            for (int f = 0; f < 16; f++) {
                float2 bq = bq2[4 * f + tig];
                float s0 = fmaf(-2.0f, acc[f][0], bq.x);
                float s1 = fmaf(-2.0f, acc[f][1], bq.y);
                float s2 = fmaf(-2.0f, acc[f][2], bq.x);
                float s3 = fmaf(-2.0f, acc[f][3], bq.y);
                top9_insert(s0, heap0, thr0);
                top9_insert(s1, heap0, thr0);
                top9_insert(s2, heap1, thr1);
                top9_insert(s3, heap1, thr1);
            }
        }

        // ---- all warps done reading buf -> refill it with tile t+2
        __syncthreads();
        if (t + 2 < T_TILES)
            issue_B_loads(sm, buf, nbeg + (t + 2) * NTILE, tid, buf);
        cp_commit();
    }

    // ---- write partial top-9 lists: list = blockIdx.y*4 + tig
    {
        const int list = blockIdx.y * 4 + tig;
        const int row0 = qbase + wid * 16 + g;
        size_t b0 = ((size_t)list * M_Q + row0) * PART_STRIDE;
        size_t b1 = ((size_t)list * M_Q + row0 + 8) * PART_STRIDE;
#pragma unroll
        for (int r = 0; r < KNN; r++) {
            g_part[b0 + r] = heap0[r];
            g_part[b1 + r] = heap1[r];
        }
    }
}

// ---------------------------------------------------------------------------
// Finalize: merge 16 partial lists (144 candidates) -> top-9, sqrt, mean
// ---------------------------------------------------------------------------
__global__ void knn_finalize_kernel(float* __restrict__ out) {
    int qi = blockIdx.x * blockDim.x + threadIdx.x;
    if (qi >= M_Q) return;
    float v[NLISTS * KNN];
#pragma unroll
    for (int l = 0; l < NLISTS; l++)
#pragma unroll
        for (int r = 0; r < KNN; r++)
            v[l * KNN + r] = g_part[((size_t)l * M_Q + qi) * PART_STRIDE + r];

    float qsq = g_qsq[qi];
    float sum = 0.0f;
#pragma unroll 1
    for (int r = 0; r < KNN; r++) {
        float m = v[0];
        int mi = 0;
#pragma unroll 1
        for (int i = 1; i < NLISTS * KNN; i++)
            if (v[i] < m) { m = v[i]; mi = i; }
        v[mi] = __int_as_float(0x7f800000);
        sum += sqrtf(fmaxf(m + qsq, 0.0f));
    }
    out[qi] = sum * (1.0f / KNN);
}

// ---------------------------------------------------------------------------
extern "C" void kernel_launch(void* const* d_in, const int* in_sizes, int n_in,
                              void* d_out, int out_size)
{
    const float* q = (const float*)d_in[0];   // features    [4096,128]
    const float* b = (const float*)d_in[1];   // memory_bank [65536,128]
    if (n_in >= 2 && in_sizes[0] > in_sizes[1]) {   // defensive ordering
        const float* tmp = q; q = b; b = tmp;
    }
    float* out = (float*)d_out;

    static __half2* p_bh = nullptr;
    static __half2* p_qh = nullptr;
    static float *p_bsq = nullptr, *p_qsq = nullptr;
    if (!p_bh) {
        cudaGetSymbolAddress((void**)&p_bh, g_bh);
        cudaGetSymbolAddress((void**)&p_qh, g_qh);
        cudaGetSymbolAddress((void**)&p_bsq, g_bsq);
        cudaGetSymbolAddress((void**)&p_qsq, g_qsq);
    }

    cudaFuncSetAttribute(knn_main_kernel,
                         cudaFuncAttributeMaxDynamicSharedMemorySize, SMEM_SZ);

    to_half_kernel<<<(N_B * D_DIM / 4 + 255) / 256, 256>>>((const float4*)b, p_bh, N_B * D_DIM / 4);
    to_half_kernel<<<(M_Q * D_DIM / 4 + 255) / 256, 256>>>((const float4*)q, p_qh, M_Q * D_DIM / 4);
    norms_kernel<<<N_B / 8, 256>>>((const float4*)b, p_bsq, N_B);
    norms_kernel<<<M_Q / 8, 256>>>((const float4*)q, p_qsq, M_Q);

    dim3 grid(M_Q / MTILE, NSPLIT);
    knn_main_kernel<<<grid, THREADS, SMEM_SZ>>>();

    knn_finalize_kernel<<<M_Q / 256, 256>>>(out);
}

// round 4
// speedup vs baseline: 1.9984x; 1.0489x over previous
#include <cuda_runtime.h>
#include <cuda_fp16.h>
#include <cstdint>

#define M_Q   4096
#define N_B   65536
#define D_DIM 128
#define KNN   9
#define MTILE 128
#define NTILE 128
#define NSPLIT 4
#define NPART (N_B / NSPLIT)          // 16384
#define T_TILES (NPART / NTILE)       // 128
#define THREADS 256
#define PART_STRIDE 12
#define NLISTS 16                     // 4 N-splits x 4 lanes-per-row
#define TILE_HALFS (128 * D_DIM)      // 16384 halves = 32KB per packed tile

// ---------------------------------------------------------------------------
// Device-global scratch (no allocation allowed)
// ---------------------------------------------------------------------------
__device__ __align__(16) float g_bsq[N_B];
__device__ __align__(16) float g_qsq[M_Q];
__device__ __align__(16) float g_part[NLISTS * M_Q * PART_STRIDE];
// tile-major, pre-swizzled fp16 copies (ready for 32KB bulk copy into smem)
__device__ __align__(16) __half g_bt[(size_t)N_B * D_DIM];
__device__ __align__(16) __half g_qt[(size_t)M_Q * D_DIM];

// ---------------------------------------------------------------------------
// SMEM: A tile 32KB, B tiles 2x32KB, bsq 2x512B, mbarriers
// ---------------------------------------------------------------------------
#define OFF_A    0
#define OFF_B    32768
#define OFF_BSQ  (32768 + 2 * 32768)        // 98304
#define OFF_MBAR (OFF_BSQ + 2 * 512)        // 99328
#define SMEM_SZ  (OFF_MBAR + 64)

// ---------------------------------------------------------------------------
// PTX helpers (sm_90-baseline only; nothing 'a'-gated)
// ---------------------------------------------------------------------------
__device__ __forceinline__ uint32_t smem_u32(const void* p) {
    uint32_t a;
    asm("{ .reg .u64 t; cvta.to.shared.u64 t, %1; cvt.u32.u64 %0, t; }" : "=r"(a) : "l"(p));
    return a;
}
__device__ __forceinline__ void ldsm4(uint32_t* r, uint32_t addr) {
    asm volatile("ldmatrix.sync.aligned.m8n8.x4.shared.b16 {%0,%1,%2,%3}, [%4];"
                 : "=r"(r[0]), "=r"(r[1]), "=r"(r[2]), "=r"(r[3]) : "r"(addr));
}
__device__ __forceinline__ void mma16816(float* c, const uint32_t* a, const uint32_t* b) {
    asm volatile(
        "mma.sync.aligned.m16n8k16.row.col.f32.f16.f16.f32 "
        "{%0,%1,%2,%3}, {%4,%5,%6,%7}, {%8,%9}, {%0,%1,%2,%3};"
        : "+f"(c[0]), "+f"(c[1]), "+f"(c[2]), "+f"(c[3])
        : "r"(a[0]), "r"(a[1]), "r"(a[2]), "r"(a[3]), "r"(b[0]), "r"(b[1]));
}
#define MBAR_INIT(a, c) \
    asm volatile("mbarrier.init.shared.b64 [%0], %1;" :: "r"(a), "r"(c) : "memory")
#define MBAR_EXPECT_TX(a, tx) \
    asm volatile("mbarrier.arrive.expect_tx.shared.b64 _, [%0], %1;" :: "r"(a), "r"(tx) : "memory")
#define MBAR_WAIT(a, ph) do {                                                   \
    asm volatile(                                                               \
        "{\n\t.reg .pred P1;\n\t"                                               \
        "WAIT_LOOP_%=:\n\t"                                                     \
        "mbarrier.try_wait.parity.acquire.cta.shared::cta.b64 P1, [%0], %1, 0x989680;\n\t" \
        "@P1 bra.uni WAIT_DONE_%=;\n\t"                                         \
        "bra.uni WAIT_LOOP_%=;\n\t"                                             \
        "WAIT_DONE_%=:\n\t}"                                                    \
        :: "r"(a), "r"(ph) : "memory");                                         \
} while (0)
__device__ __forceinline__ void bulk_g2s(uint32_t dst, const void* src,
                                         uint32_t bytes, uint32_t mbar) {
    asm volatile(
        "cp.async.bulk.shared::cluster.global.mbarrier::complete_tx::bytes "
        "[%0], [%1], %2, [%3];"
        :: "r"(dst), "l"(src), "r"(bytes), "r"(mbar) : "memory");
}

// ---------------------------------------------------------------------------
// Pre-pass: convert fp32 -> fp16, pack into tile-major pre-swizzled layout.
// Chunk i (16B of output) = vector vec = i>>4, 16B-column c = i&15.
// Output byte offset = tile*32768 + r*256 + ((c ^ (r&7))<<4), r = vec & 127.
// ---------------------------------------------------------------------------
__global__ void pack_tiles_kernel(const float4* __restrict__ src,
                                  uint4* __restrict__ dst, int nchunks) {
    int i = blockIdx.x * blockDim.x + threadIdx.x;
    if (i >= nchunks) return;
    int vec = i >> 4, c = i & 15;
    int tile = vec >> 7, r = vec & 127;
    float4 a = src[2 * i];
    float4 b = src[2 * i + 1];
    __half2 h0 = __floats2half2_rn(a.x, a.y);
    __half2 h1 = __floats2half2_rn(a.z, a.w);
    __half2 h2 = __floats2half2_rn(b.x, b.y);
    __half2 h3 = __floats2half2_rn(b.z, b.w);
    uint4 o;
    o.x = *(uint32_t*)&h0; o.y = *(uint32_t*)&h1;
    o.z = *(uint32_t*)&h2; o.w = *(uint32_t*)&h3;
    uint32_t off = (uint32_t)tile * 32768 + r * 256 + (((uint32_t)(c ^ (r & 7))) << 4);
    dst[off >> 4] = o;
}

__global__ void norms_kernel(const float4* __restrict__ data, float* __restrict__ out, int nvec) {
    int gw = (blockIdx.x * blockDim.x + threadIdx.x) >> 5;
    int lane = threadIdx.x & 31;
    if (gw >= nvec) return;
    float4 d = data[gw * 32 + lane];
    float s = d.x * d.x + d.y * d.y + d.z * d.z + d.w * d.w;
#pragma unroll
    for (int off = 16; off; off >>= 1) s += __shfl_xor_sync(0xffffffffu, s, off);
    if (lane == 0) out[gw] = s;
}

// ---------------------------------------------------------------------------
// Streaming top-9 (registers only)
// ---------------------------------------------------------------------------
__device__ __forceinline__ void top9_insert(float s, float (&heap)[KNN], float& thr) {
    if (s < thr) {
        bool done = false;
#pragma unroll
        for (int i = 0; i < KNN; i++)
            if (!done && heap[i] == thr) { heap[i] = s; done = true; }
        float m = heap[0];
#pragma unroll
        for (int i = 1; i < KNN; i++) m = fmaxf(m, heap[i]);
        thr = m;
    }
}

// ---------------------------------------------------------------------------
// Main kernel: bulk-TMA pipeline + fp16 mma.sync GEMM + streaming top-9
// grid = (32, NSPLIT), 256 threads; warp w owns rows w*16..w*16+15
// ---------------------------------------------------------------------------
__global__ void __launch_bounds__(THREADS, 1) knn_main_kernel() {
    extern __shared__ char smem[];
    const uint32_t sm = smem_u32(smem);
    const int tid  = threadIdx.x;
    const int wid  = tid >> 5;
    const int lane = tid & 31;
    const int g    = lane >> 2;
    const int tig  = lane & 3;
    const int qtile = blockIdx.x;
    const int qbase = qtile * MTILE;
    const int nbeg  = blockIdx.y * NPART;
    const int btile0 = nbeg >> 7;          // first packed B tile index
    const float INF = __int_as_float(0x7f800000);

    // ---- mbarrier init
    if (tid == 0) { MBAR_INIT(sm + OFF_MBAR, 1); MBAR_INIT(sm + OFF_MBAR + 8, 1); }
    __syncthreads();

    // ---- prologue: stage0 = A + B0 + bsq0 ; stage1 = B1 + bsq1
    if (tid == 0) {
        MBAR_EXPECT_TX(sm + OFF_MBAR, 32768u + 32768u + 512u);
        bulk_g2s(sm + OFF_A, g_qt + (size_t)qtile * TILE_HALFS, 32768u, sm + OFF_MBAR);
        bulk_g2s(sm + OFF_B, g_bt + (size_t)btile0 * TILE_HALFS, 32768u, sm + OFF_MBAR);
        bulk_g2s(sm + OFF_BSQ, g_bsq + nbeg, 512u, sm + OFF_MBAR);
        MBAR_EXPECT_TX(sm + OFF_MBAR + 8, 32768u + 512u);
        bulk_g2s(sm + OFF_B + 32768, g_bt + (size_t)(btile0 + 1) * TILE_HALFS, 32768u,
                 sm + OFF_MBAR + 8);
        bulk_g2s(sm + OFF_BSQ + 512, g_bsq + nbeg + NTILE, 512u, sm + OFF_MBAR + 8);
    }

    // ---- wait stage0 (A + B0), preload A fragments
    MBAR_WAIT(sm + OFF_MBAR, 0);

    uint32_t aF[8][4];
    {
        const int m0 = wid * 16;
        const int rbase = lane & 15;
        const int shi = lane >> 4;
        const int rsw = rbase & 7;
        const uint32_t arow = sm + OFF_A + (m0 + rbase) * 256;
#pragma unroll
        for (int s = 0; s < 8; s++)
            ldsm4(aF[s], arow + (((2 * s + shi) ^ rsw) << 4));
    }

    float heap0[KNN], heap1[KNN];
    float thr0 = INF, thr1 = INF;
#pragma unroll
    for (int i = 0; i < KNN; i++) { heap0[i] = INF; heap1[i] = INF; }

    const int rbaseB = (lane & 7) + ((lane >> 4) << 3);
    const int shiB   = (lane >> 3) & 1;
    const int rswB   = lane & 7;

#pragma unroll 1
    for (int t = 0; t < T_TILES; t++) {
        const int buf = t & 1;

        if (t > 0) MBAR_WAIT(sm + OFF_MBAR + buf * 8, (t >> 1) & 1);

        // ---- GEMM: warp = 16 rows x 128 cols x K=128
        float acc[16][4];
#pragma unroll
        for (int f = 0; f < 16; f++)
#pragma unroll
            for (int x = 0; x < 4; x++) acc[f][x] = 0.0f;

        const uint32_t Bb = sm + OFF_B + buf * 32768 + rbaseB * 256;
#pragma unroll
        for (int s = 0; s < 8; s++) {
            const uint32_t segoff = ((2 * s + shiB) ^ rswB) << 4;
#pragma unroll
            for (int j = 0; j < 8; j++) {
                uint32_t b[4];
                ldsm4(b, Bb + j * 4096 + segoff);
                mma16816(acc[2 * j],     aF[s], b);
                mma16816(acc[2 * j + 1], aF[s], b + 2);
            }
        }

        // ---- epilogue: key = bsq - 2*dot, streaming top-9
        {
            const float2* bq2 = (const float2*)(smem + OFF_BSQ + buf * 512);
#pragma unroll
            for (int f = 0; f < 16; f++) {
                float2 bq = bq2[4 * f + tig];
                float s0 = fmaf(-2.0f, acc[f][0], bq.x);
                float s1 = fmaf(-2.0f, acc[f][1], bq.y);
                float s2 = fmaf(-2.0f, acc[f][2], bq.x);
                float s3 = fmaf(-2.0f, acc[f][3], bq.y);
                top9_insert(s0, heap0, thr0);
                top9_insert(s1, heap0, thr0);
                top9_insert(s2, heap1, thr1);
                top9_insert(s3, heap1, thr1);
            }
        }

        // ---- buf fully consumed -> refill with tile t+2
        __syncthreads();
        if (t + 2 < T_TILES && tid == 0) {
            MBAR_EXPECT_TX(sm + OFF_MBAR + buf * 8, 32768u + 512u);
            bulk_g2s(sm + OFF_B + buf * 32768,
                     g_bt + (size_t)(btile0 + t + 2) * TILE_HALFS, 32768u,
                     sm + OFF_MBAR + buf * 8);
            bulk_g2s(sm + OFF_BSQ + buf * 512, g_bsq + nbeg + (t + 2) * NTILE, 512u,
                     sm + OFF_MBAR + buf * 8);
        }
    }

    // ---- write partial top-9 lists: list = blockIdx.y*4 + tig
    {
        const int list = blockIdx.y * 4 + tig;
        const int row0 = qbase + wid * 16 + g;
        size_t b0 = ((size_t)list * M_Q + row0) * PART_STRIDE;
        size_t b1 = ((size_t)list * M_Q + row0 + 8) * PART_STRIDE;
#pragma unroll
        for (int r = 0; r < KNN; r++) {
            g_part[b0 + r] = heap0[r];
            g_part[b1 + r] = heap1[r];
        }
    }
}

// ---------------------------------------------------------------------------
// Finalize: merge 16 partial lists (144 candidates) -> top-9, sqrt, mean
// ---------------------------------------------------------------------------
__global__ void knn_finalize_kernel(float* __restrict__ out) {
    int qi = blockIdx.x * blockDim.x + threadIdx.x;
    if (qi >= M_Q) return;
    float v[NLISTS * KNN];
#pragma unroll
    for (int l = 0; l < NLISTS; l++)
#pragma unroll
        for (int r = 0; r < KNN; r++)
            v[l * KNN + r] = g_part[((size_t)l * M_Q + qi) * PART_STRIDE + r];

    float qsq = g_qsq[qi];
    float sum = 0.0f;
#pragma unroll 1
    for (int r = 0; r < KNN; r++) {
        float m = v[0];
        int mi = 0;
#pragma unroll 1
        for (int i = 1; i < NLISTS * KNN; i++)
            if (v[i] < m) { m = v[i]; mi = i; }
        v[mi] = __int_as_float(0x7f800000);
        sum += sqrtf(fmaxf(m + qsq, 0.0f));
    }
    out[qi] = sum * (1.0f / KNN);
}

// ---------------------------------------------------------------------------
extern "C" void kernel_launch(void* const* d_in, const int* in_sizes, int n_in,
                              void* d_out, int out_size)
{
    const float* q = (const float*)d_in[0];   // features    [4096,128]
    const float* b = (const float*)d_in[1];   // memory_bank [65536,128]
    if (n_in >= 2 && in_sizes[0] > in_sizes[1]) {   // defensive ordering
        const float* tmp = q; q = b; b = tmp;
    }
    float* out = (float*)d_out;

    static uint4* p_bt = nullptr;
    static uint4* p_qt = nullptr;
    static float *p_bsq = nullptr, *p_qsq = nullptr;
    if (!p_bt) {
        cudaGetSymbolAddress((void**)&p_bt, g_bt);
        cudaGetSymbolAddress((void**)&p_qt, g_qt);
        cudaGetSymbolAddress((void**)&p_bsq, g_bsq);
        cudaGetSymbolAddress((void**)&p_qsq, g_qsq);
    }

    cudaFuncSetAttribute(knn_main_kernel,
                         cudaFuncAttributeMaxDynamicSharedMemorySize, SMEM_SZ);

    const int bchunks = N_B * 16;   // 16B output chunks
    const int qchunks = M_Q * 16;
    pack_tiles_kernel<<<bchunks / 256, 256>>>((const float4*)b, p_bt, bchunks);
    pack_tiles_kernel<<<qchunks / 256, 256>>>((const float4*)q, p_qt, qchunks);
    norms_kernel<<<N_B / 8, 256>>>((const float4*)b, p_bsq, N_B);
    norms_kernel<<<M_Q / 8, 256>>>((const float4*)q, p_qsq, M_Q);

    dim3 grid(M_Q / MTILE, NSPLIT);
    knn_main_kernel<<<grid, THREADS, SMEM_SZ>>>();

    knn_finalize_kernel<<<M_Q / 256, 256>>>(out);
}

// round 5
// speedup vs baseline: 2.5091x; 1.2556x over previous
#include <cuda_runtime.h>
#include <cuda_fp16.h>
#include <cstdint>

#define M_Q   4096
#define N_B   65536
#define D_DIM 128
#define KNN   9
#define MTILE 128
#define NTILE 128
#define NSPLIT 9                      // n-splits (one-wave grid: 32*9=288 CTAs)
#define NT_TOTAL (N_B / NTILE)        // 512 total n-tiles
#define THREADS 256
#define PART_STRIDE 12
#define NLISTS NSPLIT
#define TILE_HALFS (128 * D_DIM)      // 16384 halves = 32KB per packed tile

// ---------------------------------------------------------------------------
// Device-global scratch (no allocation allowed)
// ---------------------------------------------------------------------------
__device__ __align__(16) float g_bsq[N_B];
__device__ __align__(16) float g_qsq[M_Q];
__device__ __align__(16) float g_part[NLISTS * M_Q * PART_STRIDE];
// tile-major, pre-swizzled fp16 copies (ready for 32KB bulk copy into smem)
__device__ __align__(16) __half g_bt[(size_t)N_B * D_DIM];
__device__ __align__(16) __half g_qt[(size_t)M_Q * D_DIM];

// ---------------------------------------------------------------------------
// SMEM: A tile 32KB, B tiles 2x32KB, bsq 2x512B, mbarriers  (99392 B/CTA)
// ---------------------------------------------------------------------------
#define OFF_A    0
#define OFF_B    32768
#define OFF_BSQ  (32768 + 2 * 32768)        // 98304
#define OFF_MBAR (OFF_BSQ + 2 * 512)        // 99328
#define SMEM_SZ  (OFF_MBAR + 64)

// ---------------------------------------------------------------------------
// PTX helpers (sm_90-baseline only; nothing 'a'-gated)
// ---------------------------------------------------------------------------
__device__ __forceinline__ uint32_t smem_u32(const void* p) {
    uint32_t a;
    asm("{ .reg .u64 t; cvta.to.shared.u64 t, %1; cvt.u32.u64 %0, t; }" : "=r"(a) : "l"(p));
    return a;
}
__device__ __forceinline__ void ldsm4(uint32_t* r, uint32_t addr) {
    asm volatile("ldmatrix.sync.aligned.m8n8.x4.shared.b16 {%0,%1,%2,%3}, [%4];"
                 : "=r"(r[0]), "=r"(r[1]), "=r"(r[2]), "=r"(r[3]) : "r"(addr));
}
__device__ __forceinline__ void mma16816(float* c, const uint32_t* a, const uint32_t* b) {
    asm volatile(
        "mma.sync.aligned.m16n8k16.row.col.f32.f16.f16.f32 "
        "{%0,%1,%2,%3}, {%4,%5,%6,%7}, {%8,%9}, {%0,%1,%2,%3};"
        : "+f"(c[0]), "+f"(c[1]), "+f"(c[2]), "+f"(c[3])
        : "r"(a[0]), "r"(a[1]), "r"(a[2]), "r"(a[3]), "r"(b[0]), "r"(b[1]));
}
#define MBAR_INIT(a, c) \
    asm volatile("mbarrier.init.shared.b64 [%0], %1;" :: "r"(a), "r"(c) : "memory")
#define MBAR_EXPECT_TX(a, tx) \
    asm volatile("mbarrier.arrive.expect_tx.shared.b64 _, [%0], %1;" :: "r"(a), "r"(tx) : "memory")
#define MBAR_WAIT(a, ph) do {                                                   \
    asm volatile(                                                               \
        "{\n\t.reg .pred P1;\n\t"                                               \
        "WAIT_LOOP_%=:\n\t"                                                     \
        "mbarrier.try_wait.parity.acquire.cta.shared::cta.b64 P1, [%0], %1, 0x989680;\n\t" \
        "@P1 bra.uni WAIT_DONE_%=;\n\t"                                         \
        "bra.uni WAIT_LOOP_%=;\n\t"                                             \
        "WAIT_DONE_%=:\n\t}"                                                    \
        :: "r"(a), "r"(ph) : "memory");                                         \
} while (0)
__device__ __forceinline__ void bulk_g2s(uint32_t dst, const void* src,
                                         uint32_t bytes, uint32_t mbar) {
    asm volatile(
        "cp.async.bulk.shared::cluster.global.mbarrier::complete_tx::bytes "
        "[%0], [%1], %2, [%3];"
        :: "r"(dst), "l"(src), "r"(bytes), "r"(mbar) : "memory");
}

// ---------------------------------------------------------------------------
// Pre-pass: fp32 -> fp16, packed tile-major pre-swizzled layout
// ---------------------------------------------------------------------------
__global__ void pack_tiles_kernel(const float4* __restrict__ src,
                                  uint4* __restrict__ dst, int nchunks) {
    int i = blockIdx.x * blockDim.x + threadIdx.x;
    if (i >= nchunks) return;
    int vec = i >> 4, c = i & 15;
    int tile = vec >> 7, r = vec & 127;
    float4 a = src[2 * i];
    float4 b = src[2 * i + 1];
    __half2 h0 = __floats2half2_rn(a.x, a.y);
    __half2 h1 = __floats2half2_rn(a.z, a.w);
    __half2 h2 = __floats2half2_rn(b.x, b.y);
    __half2 h3 = __floats2half2_rn(b.z, b.w);
    uint4 o;
    o.x = *(uint32_t*)&h0; o.y = *(uint32_t*)&h1;
    o.z = *(uint32_t*)&h2; o.w = *(uint32_t*)&h3;
    uint32_t off = (uint32_t)tile * 32768 + r * 256 + (((uint32_t)(c ^ (r & 7))) << 4);
    dst[off >> 4] = o;
}

__global__ void norms_kernel(const float4* __restrict__ data, float* __restrict__ out, int nvec) {
    int gw = (blockIdx.x * blockDim.x + threadIdx.x) >> 5;
    int lane = threadIdx.x & 31;
    if (gw >= nvec) return;
    float4 d = data[gw * 32 + lane];
    float s = d.x * d.x + d.y * d.y + d.z * d.z + d.w * d.w;
#pragma unroll
    for (int off = 16; off; off >>= 1) s += __shfl_xor_sync(0xffffffffu, s, off);
    if (lane == 0) out[gw] = s;
}

// ---------------------------------------------------------------------------
// Streaming top-9 (registers only)
// ---------------------------------------------------------------------------
__device__ __forceinline__ void top9_insert(float s, float (&heap)[KNN], float& thr) {
    if (s < thr) {
        bool done = false;
#pragma unroll
        for (int i = 0; i < KNN; i++)
            if (!done && heap[i] == thr) { heap[i] = s; done = true; }
        float m = heap[0];
#pragma unroll
        for (int i = 1; i < KNN; i++) m = fmaxf(m, heap[i]);
        thr = m;
    }
}

// ---------------------------------------------------------------------------
// Main kernel: occupancy-2 TMA pipeline + fp16 mma.sync + streaming top-9
// grid = (32, 9): CTA y handles n-tiles [512y/9, 512(y+1)/9)
// ---------------------------------------------------------------------------
__global__ void __launch_bounds__(THREADS, 2) knn_main_kernel() {
    extern __shared__ char smem[];
    const uint32_t sm = smem_u32(smem);
    const int tid  = threadIdx.x;
    const int wid  = tid >> 5;
    const int lane = tid & 31;
    const int g    = lane >> 2;
    const int tig  = lane & 3;
    const int qtile = blockIdx.x;
    const int qbase = qtile * MTILE;
    const int b0  = (NT_TOTAL * blockIdx.y) / NSPLIT;       // first n-tile
    const int cnt = (NT_TOTAL * (blockIdx.y + 1)) / NSPLIT - b0;  // 56 or 57
    const float INF = __int_as_float(0x7f800000);

    if (tid == 0) { MBAR_INIT(sm + OFF_MBAR, 1); MBAR_INIT(sm + OFF_MBAR + 8, 1); }
    __syncthreads();

    // ---- prologue: stage0 = A + B[b0] + bsq ; stage1 = B[b0+1] + bsq
    if (tid == 0) {
        MBAR_EXPECT_TX(sm + OFF_MBAR, 32768u + 32768u + 512u);
        bulk_g2s(sm + OFF_A, g_qt + (size_t)qtile * TILE_HALFS, 32768u, sm + OFF_MBAR);
        bulk_g2s(sm + OFF_B, g_bt + (size_t)b0 * TILE_HALFS, 32768u, sm + OFF_MBAR);
        bulk_g2s(sm + OFF_BSQ, g_bsq + b0 * NTILE, 512u, sm + OFF_MBAR);
        MBAR_EXPECT_TX(sm + OFF_MBAR + 8, 32768u + 512u);
        bulk_g2s(sm + OFF_B + 32768, g_bt + (size_t)(b0 + 1) * TILE_HALFS, 32768u,
                 sm + OFF_MBAR + 8);
        bulk_g2s(sm + OFF_BSQ + 512, g_bsq + (b0 + 1) * NTILE, 512u, sm + OFF_MBAR + 8);
    }

    MBAR_WAIT(sm + OFF_MBAR, 0);

    // preload A fragments (reused for all tiles)
    uint32_t aF[8][4];
    {
        const int m0 = wid * 16;
        const int rbase = lane & 15;
        const int shi = lane >> 4;
        const int rsw = rbase & 7;
        const uint32_t arow = sm + OFF_A + (m0 + rbase) * 256;
#pragma unroll
        for (int s = 0; s < 8; s++)
            ldsm4(aF[s], arow + (((2 * s + shi) ^ rsw) << 4));
    }

    float heap0[KNN], heap1[KNN];
    float thr0 = INF, thr1 = INF;
#pragma unroll
    for (int i = 0; i < KNN; i++) { heap0[i] = INF; heap1[i] = INF; }

    const int rbaseB = (lane & 7) + ((lane >> 4) << 3);
    const int shiB   = (lane >> 3) & 1;
    const int rswB   = lane & 7;

#pragma unroll 1
    for (int t = 0; t < cnt; t++) {
        const int buf = t & 1;

        if (t > 0) MBAR_WAIT(sm + OFF_MBAR + buf * 8, (t >> 1) & 1);

        const uint32_t Bb = sm + OFF_B + buf * 32768 + rbaseB * 256;
        const float2* bq2 = (const float2*)(smem + OFF_BSQ + buf * 512);

        // two column halves (acc live-range halved -> fits 2 CTAs/SM)
#pragma unroll
        for (int half = 0; half < 2; half++) {
            float acc[8][4];
#pragma unroll
            for (int f = 0; f < 8; f++)
#pragma unroll
                for (int x = 0; x < 4; x++) acc[f][x] = 0.0f;

#pragma unroll
            for (int s = 0; s < 8; s++) {
                const uint32_t segoff = ((2 * s + shiB) ^ rswB) << 4;
#pragma unroll
                for (int j = 0; j < 4; j++) {
                    uint32_t b[4];
                    ldsm4(b, Bb + (half * 4 + j) * 4096 + segoff);
                    mma16816(acc[2 * j],     aF[s], b);
                    mma16816(acc[2 * j + 1], aF[s], b + 2);
                }
            }

#pragma unroll
            for (int f = 0; f < 8; f++) {
                float2 bq = bq2[4 * (half * 8 + f) + tig];
                float s0 = fmaf(-2.0f, acc[f][0], bq.x);
                float s1 = fmaf(-2.0f, acc[f][1], bq.y);
                float s2 = fmaf(-2.0f, acc[f][2], bq.x);
                float s3 = fmaf(-2.0f, acc[f][3], bq.y);
                top9_insert(s0, heap0, thr0);
                top9_insert(s1, heap0, thr0);
                top9_insert(s2, heap1, thr1);
                top9_insert(s3, heap1, thr1);
            }
        }

        __syncthreads();
        if (t + 2 < cnt && tid == 0) {
            MBAR_EXPECT_TX(sm + OFF_MBAR + buf * 8, 32768u + 512u);
            bulk_g2s(sm + OFF_B + buf * 32768,
                     g_bt + (size_t)(b0 + t + 2) * TILE_HALFS, 32768u,
                     sm + OFF_MBAR + buf * 8);
            bulk_g2s(sm + OFF_BSQ + buf * 512, g_bsq + (b0 + t + 2) * NTILE, 512u,
                     sm + OFF_MBAR + buf * 8);
        }
    }

    // ---- quad merge: lanes tig=1..3 ship their heaps to tig=0
    const unsigned FULL = 0xffffffffu;
#pragma unroll
    for (int src = 1; src < 4; src++) {
#pragma unroll
        for (int i = 0; i < KNN; i++) {
            float v0 = __shfl_sync(FULL, heap0[i], (lane & ~3) + src);
            float v1 = __shfl_sync(FULL, heap1[i], (lane & ~3) + src);
            if (tig == 0) {
                top9_insert(v0, heap0, thr0);
                top9_insert(v1, heap1, thr1);
            }
        }
    }

    // ---- write merged top-9 (one list per CTA n-split)
    if (tig == 0) {
        const int row0 = qbase + wid * 16 + g;
        size_t p0 = ((size_t)blockIdx.y * M_Q + row0) * PART_STRIDE;
        size_t p1 = ((size_t)blockIdx.y * M_Q + row0 + 8) * PART_STRIDE;
#pragma unroll
        for (int r = 0; r < KNN; r++) {
            g_part[p0 + r] = heap0[r];
            g_part[p1 + r] = heap1[r];
        }
    }
}

// ---------------------------------------------------------------------------
// Finalize: stream 9 lists x 9 = 81 candidates through a register heap
// ---------------------------------------------------------------------------
__global__ void knn_finalize_kernel(float* __restrict__ out) {
    int qi = blockIdx.x * blockDim.x + threadIdx.x;
    if (qi >= M_Q) return;
    const float INF = __int_as_float(0x7f800000);
    float heap[KNN], thr = INF;
#pragma unroll
    for (int i = 0; i < KNN; i++) heap[i] = INF;

#pragma unroll 1
    for (int l = 0; l < NLISTS; l++) {
        const float* p = &g_part[((size_t)l * M_Q + qi) * PART_STRIDE];
#pragma unroll
        for (int r = 0; r < KNN; r++) top9_insert(p[r], heap, thr);
    }

    float qsq = g_qsq[qi];
    float sum = 0.0f;
#pragma unroll
    for (int i = 0; i < KNN; i++) sum += sqrtf(fmaxf(heap[i] + qsq, 0.0f));
    out[qi] = sum * (1.0f / KNN);
}

// ---------------------------------------------------------------------------
extern "C" void kernel_launch(void* const* d_in, const int* in_sizes, int n_in,
                              void* d_out, int out_size)
{
    const float* q = (const float*)d_in[0];   // features    [4096,128]
    const float* b = (const float*)d_in[1];   // memory_bank [65536,128]
    if (n_in >= 2 && in_sizes[0] > in_sizes[1]) {   // defensive ordering
        const float* tmp = q; q = b; b = tmp;
    }
    float* out = (float*)d_out;

    static uint4* p_bt = nullptr;
    static uint4* p_qt = nullptr;
    static float *p_bsq = nullptr, *p_qsq = nullptr;
    if (!p_bt) {
        cudaGetSymbolAddress((void**)&p_bt, g_bt);
        cudaGetSymbolAddress((void**)&p_qt, g_qt);
        cudaGetSymbolAddress((void**)&p_bsq, g_bsq);
        cudaGetSymbolAddress((void**)&p_qsq, g_qsq);
    }

    cudaFuncSetAttribute(knn_main_kernel,
                         cudaFuncAttributeMaxDynamicSharedMemorySize, SMEM_SZ);

    const int bchunks = N_B * 16;
    const int qchunks = M_Q * 16;
    pack_tiles_kernel<<<bchunks / 256, 256>>>((const float4*)b, p_bt, bchunks);
    pack_tiles_kernel<<<qchunks / 256, 256>>>((const float4*)q, p_qt, qchunks);
    norms_kernel<<<N_B / 8, 256>>>((const float4*)b, p_bsq, N_B);
    norms_kernel<<<M_Q / 8, 256>>>((const float4*)q, p_qsq, M_Q);

    dim3 grid(M_Q / MTILE, NSPLIT);
    knn_main_kernel<<<grid, THREADS, SMEM_SZ>>>();

    knn_finalize_kernel<<<M_Q / 256, 256>>>(out);
}

// round 6
// speedup vs baseline: 2.5479x; 1.0154x over previous
#include <cuda_runtime.h>
#include <cuda_fp16.h>
#include <cstdint>

#define M_Q   4096
#define N_B   65536
#define D_DIM 128
#define KNN   9
#define MTILE 128
#define NTILE 128
#define NSPLIT 9                      // n-splits (one-wave grid: 32*9=288 CTAs)
#define NT_TOTAL (N_B / NTILE)        // 512 total n-tiles
#define THREADS 256
#define PART_STRIDE 12
#define NLISTS NSPLIT
#define TILE_HALFS (128 * D_DIM)      // 16384 halves = 32KB per packed tile

// ---------------------------------------------------------------------------
// Device-global scratch (no allocation allowed)
// ---------------------------------------------------------------------------
__device__ __align__(16) float g_bsq[N_B];
__device__ __align__(16) float g_qsq[M_Q];
__device__ __align__(16) float g_part[NLISTS * M_Q * PART_STRIDE];
// tile-major, pre-swizzled fp16 copies (ready for 32KB bulk copy into smem)
__device__ __align__(16) __half g_bt[(size_t)N_B * D_DIM];
__device__ __align__(16) __half g_qt[(size_t)M_Q * D_DIM];

// ---------------------------------------------------------------------------
// SMEM: A tile 32KB, B tiles 2x32KB, bsq 2x512B, mbarriers  (99392 B/CTA)
// ---------------------------------------------------------------------------
#define OFF_A    0
#define OFF_B    32768
#define OFF_BSQ  (32768 + 2 * 32768)        // 98304
#define OFF_MBAR (OFF_BSQ + 2 * 512)        // 99328
#define SMEM_SZ  (OFF_MBAR + 64)

// ---------------------------------------------------------------------------
// PTX helpers (sm_90-baseline only; nothing 'a'-gated)
// ---------------------------------------------------------------------------
__device__ __forceinline__ uint32_t smem_u32(const void* p) {
    uint32_t a;
    asm("{ .reg .u64 t; cvta.to.shared.u64 t, %1; cvt.u32.u64 %0, t; }" : "=r"(a) : "l"(p));
    return a;
}
__device__ __forceinline__ void ldsm4(uint32_t* r, uint32_t addr) {
    asm volatile("ldmatrix.sync.aligned.m8n8.x4.shared.b16 {%0,%1,%2,%3}, [%4];"
                 : "=r"(r[0]), "=r"(r[1]), "=r"(r[2]), "=r"(r[3]) : "r"(addr));
}
// fp16-accumulator MMA: 2x legacy-path throughput vs f32 acc
__device__ __forceinline__ void mma16816_f16(uint32_t* c, const uint32_t* a, const uint32_t* b) {
    asm volatile(
        "mma.sync.aligned.m16n8k16.row.col.f16.f16.f16.f16 "
        "{%0,%1}, {%2,%3,%4,%5}, {%6,%7}, {%0,%1};"
        : "+r"(c[0]), "+r"(c[1])
        : "r"(a[0]), "r"(a[1]), "r"(a[2]), "r"(a[3]), "r"(b[0]), "r"(b[1]));
}
#define MBAR_INIT(a, c) \
    asm volatile("mbarrier.init.shared.b64 [%0], %1;" :: "r"(a), "r"(c) : "memory")
#define MBAR_EXPECT_TX(a, tx) \
    asm volatile("mbarrier.arrive.expect_tx.shared.b64 _, [%0], %1;" :: "r"(a), "r"(tx) : "memory")
#define MBAR_WAIT(a, ph) do {                                                   \
    asm volatile(                                                               \
        "{\n\t.reg .pred P1;\n\t"                                               \
        "WAIT_LOOP_%=:\n\t"                                                     \
        "mbarrier.try_wait.parity.acquire.cta.shared::cta.b64 P1, [%0], %1, 0x989680;\n\t" \
        "@P1 bra.uni WAIT_DONE_%=;\n\t"                                         \
        "bra.uni WAIT_LOOP_%=;\n\t"                                             \
        "WAIT_DONE_%=:\n\t}"                                                    \
        :: "r"(a), "r"(ph) : "memory");                                         \
} while (0)
__device__ __forceinline__ void bulk_g2s(uint32_t dst, const void* src,
                                         uint32_t bytes, uint32_t mbar) {
    asm volatile(
        "cp.async.bulk.shared::cluster.global.mbarrier::complete_tx::bytes "
        "[%0], [%1], %2, [%3];"
        :: "r"(dst), "l"(src), "r"(bytes), "r"(mbar) : "memory");
}

// ---------------------------------------------------------------------------
// Pre-pass: fp32 -> fp16 packed pre-swizzled tiles + fused squared norms.
// Thread i handles 32B of input (8 floats) = 16B-chunk c of vector vec.
// 16 consecutive threads = one vector -> half-warp-wide norm reduction.
// ---------------------------------------------------------------------------
__global__ void pack_norms_kernel(const float4* __restrict__ src,
                                  uint4* __restrict__ dst,
                                  float* __restrict__ nrm, int nchunks) {
    int i = blockIdx.x * blockDim.x + threadIdx.x;
    if (i >= nchunks) return;
    int vec = i >> 4, c = i & 15;
    int tile = vec >> 7, r = vec & 127;
    float4 a = src[2 * i];
    float4 b = src[2 * i + 1];
    __half2 h0 = __floats2half2_rn(a.x, a.y);
    __half2 h1 = __floats2half2_rn(a.z, a.w);
    __half2 h2 = __floats2half2_rn(b.x, b.y);
    __half2 h3 = __floats2half2_rn(b.z, b.w);
    uint4 o;
    o.x = *(uint32_t*)&h0; o.y = *(uint32_t*)&h1;
    o.z = *(uint32_t*)&h2; o.w = *(uint32_t*)&h3;
    uint32_t off = (uint32_t)tile * 32768 + r * 256 + (((uint32_t)(c ^ (r & 7))) << 4);
    dst[off >> 4] = o;

    float s = a.x * a.x + a.y * a.y + a.z * a.z + a.w * a.w
            + b.x * b.x + b.y * b.y + b.z * b.z + b.w * b.w;
#pragma unroll
    for (int offv = 8; offv; offv >>= 1) s += __shfl_xor_sync(0xffffffffu, s, offv);
    if (c == 0) nrm[vec] = s;
}

// ---------------------------------------------------------------------------
// Streaming top-9 (registers only)
// ---------------------------------------------------------------------------
__device__ __forceinline__ void top9_insert(float s, float (&heap)[KNN], float& thr) {
    if (s < thr) {
        bool done = false;
#pragma unroll
        for (int i = 0; i < KNN; i++)
            if (!done && heap[i] == thr) { heap[i] = s; done = true; }
        float m = heap[0];
#pragma unroll
        for (int i = 1; i < KNN; i++) m = fmaxf(m, heap[i]);
        thr = m;
    }
}

// ---------------------------------------------------------------------------
// Main kernel: occ-2 TMA pipeline + fp16-acc mma.sync + streaming top-9
// grid = (32, 9): CTA y handles n-tiles [512y/9, 512(y+1)/9)
// ---------------------------------------------------------------------------
__global__ void __launch_bounds__(THREADS, 2) knn_main_kernel() {
    extern __shared__ char smem[];
    const uint32_t sm = smem_u32(smem);
    const int tid  = threadIdx.x;
    const int wid  = tid >> 5;
    const int lane = tid & 31;
    const int g    = lane >> 2;
    const int tig  = lane & 3;
    const int qtile = blockIdx.x;
    const int qbase = qtile * MTILE;
    const int b0  = (NT_TOTAL * blockIdx.y) / NSPLIT;
    const int cnt = (NT_TOTAL * (blockIdx.y + 1)) / NSPLIT - b0;
    const float INF = __int_as_float(0x7f800000);

    if (tid == 0) { MBAR_INIT(sm + OFF_MBAR, 1); MBAR_INIT(sm + OFF_MBAR + 8, 1); }
    __syncthreads();

    if (tid == 0) {
        MBAR_EXPECT_TX(sm + OFF_MBAR, 32768u + 32768u + 512u);
        bulk_g2s(sm + OFF_A, g_qt + (size_t)qtile * TILE_HALFS, 32768u, sm + OFF_MBAR);
        bulk_g2s(sm + OFF_B, g_bt + (size_t)b0 * TILE_HALFS, 32768u, sm + OFF_MBAR);
        bulk_g2s(sm + OFF_BSQ, g_bsq + b0 * NTILE, 512u, sm + OFF_MBAR);
        MBAR_EXPECT_TX(sm + OFF_MBAR + 8, 32768u + 512u);
        bulk_g2s(sm + OFF_B + 32768, g_bt + (size_t)(b0 + 1) * TILE_HALFS, 32768u,
                 sm + OFF_MBAR + 8);
        bulk_g2s(sm + OFF_BSQ + 512, g_bsq + (b0 + 1) * NTILE, 512u, sm + OFF_MBAR + 8);
    }

    MBAR_WAIT(sm + OFF_MBAR, 0);

    // preload A fragments (reused for all tiles)
    uint32_t aF[8][4];
    {
        const int m0 = wid * 16;
        const int rbase = lane & 15;
        const int shi = lane >> 4;
        const int rsw = rbase & 7;
        const uint32_t arow = sm + OFF_A + (m0 + rbase) * 256;
#pragma unroll
        for (int s = 0; s < 8; s++)
            ldsm4(aF[s], arow + (((2 * s + shi) ^ rsw) << 4));
    }

    float heap0[KNN], heap1[KNN];
    float thr0 = INF, thr1 = INF;
#pragma unroll
    for (int i = 0; i < KNN; i++) { heap0[i] = INF; heap1[i] = INF; }

    const int rbaseB = (lane & 7) + ((lane >> 4) << 3);
    const int shiB   = (lane >> 3) & 1;
    const int rswB   = lane & 7;

#pragma unroll 1
    for (int t = 0; t < cnt; t++) {
        const int buf = t & 1;

        if (t > 0) MBAR_WAIT(sm + OFF_MBAR + buf * 8, (t >> 1) & 1);

        const uint32_t Bb = sm + OFF_B + buf * 32768 + rbaseB * 256;
        const float2* bq2 = (const float2*)(smem + OFF_BSQ + buf * 512);

#pragma unroll
        for (int half = 0; half < 2; half++) {
            // fp16 packed accumulators: acc[f][0] = row g (2 cols), [1] = row g+8
            uint32_t acc[8][2];
#pragma unroll
            for (int f = 0; f < 8; f++) { acc[f][0] = 0u; acc[f][1] = 0u; }

#pragma unroll
            for (int s = 0; s < 8; s++) {
                const uint32_t segoff = ((2 * s + shiB) ^ rswB) << 4;
#pragma unroll
                for (int j = 0; j < 4; j++) {
                    uint32_t b[4];
                    ldsm4(b, Bb + (half * 4 + j) * 4096 + segoff);
                    mma16816_f16(acc[2 * j],     aF[s], b);
                    mma16816_f16(acc[2 * j + 1], aF[s], b + 2);
                }
            }

#pragma unroll
            for (int f = 0; f < 8; f++) {
                float2 bq = bq2[4 * (half * 8 + f) + tig];
                float2 v0 = __half22float2(*(const __half2*)&acc[f][0]);
                float2 v1 = __half22float2(*(const __half2*)&acc[f][1]);
                float s0 = fmaf(-2.0f, v0.x, bq.x);
                float s1 = fmaf(-2.0f, v0.y, bq.y);
                float s2 = fmaf(-2.0f, v1.x, bq.x);
                float s3 = fmaf(-2.0f, v1.y, bq.y);
                top9_insert(s0, heap0, thr0);
                top9_insert(s1, heap0, thr0);
                top9_insert(s2, heap1, thr1);
                top9_insert(s3, heap1, thr1);
            }
        }

        __syncthreads();
        if (t + 2 < cnt && tid == 0) {
            MBAR_EXPECT_TX(sm + OFF_MBAR + buf * 8, 32768u + 512u);
            bulk_g2s(sm + OFF_B + buf * 32768,
                     g_bt + (size_t)(b0 + t + 2) * TILE_HALFS, 32768u,
                     sm + OFF_MBAR + buf * 8);
            bulk_g2s(sm + OFF_BSQ + buf * 512, g_bsq + (b0 + t + 2) * NTILE, 512u,
                     sm + OFF_MBAR + buf * 8);
        }
    }

    // ---- quad merge: lanes tig=1..3 ship their heaps to tig=0
    const unsigned FULL = 0xffffffffu;
#pragma unroll
    for (int src = 1; src < 4; src++) {
#pragma unroll
        for (int i = 0; i < KNN; i++) {
            float v0 = __shfl_sync(FULL, heap0[i], (lane & ~3) + src);
            float v1 = __shfl_sync(FULL, heap1[i], (lane & ~3) + src);
            if (tig == 0) {
                top9_insert(v0, heap0, thr0);
                top9_insert(v1, heap1, thr1);
            }
        }
    }

    if (tig == 0) {
        const int row0 = qbase + wid * 16 + g;
        size_t p0 = ((size_t)blockIdx.y * M_Q + row0) * PART_STRIDE;
        size_t p1 = ((size_t)blockIdx.y * M_Q + row0 + 8) * PART_STRIDE;
#pragma unroll
        for (int r = 0; r < KNN; r++) {
            g_part[p0 + r] = heap0[r];
            g_part[p1 + r] = heap1[r];
        }
    }
}

// ---------------------------------------------------------------------------
// Finalize: stream 9 lists x 9 = 81 candidates through a register heap
// ---------------------------------------------------------------------------
__global__ void knn_finalize_kernel(float* __restrict__ out) {
    int qi = blockIdx.x * blockDim.x + threadIdx.x;
    if (qi >= M_Q) return;
    const float INF = __int_as_float(0x7f800000);
    float heap[KNN], thr = INF;
#pragma unroll
    for (int i = 0; i < KNN; i++) heap[i] = INF;

#pragma unroll 1
    for (int l = 0; l < NLISTS; l++) {
        const float* p = &g_part[((size_t)l * M_Q + qi) * PART_STRIDE];
#pragma unroll
        for (int r = 0; r < KNN; r++) top9_insert(p[r], heap, thr);
    }

    float qsq = g_qsq[qi];
    float sum = 0.0f;
#pragma unroll
    for (int i = 0; i < KNN; i++) sum += sqrtf(fmaxf(heap[i] + qsq, 0.0f));
    out[qi] = sum * (1.0f / KNN);
}

// ---------------------------------------------------------------------------
extern "C" void kernel_launch(void* const* d_in, const int* in_sizes, int n_in,
                              void* d_out, int out_size)
{
    const float* q = (const float*)d_in[0];   // features    [4096,128]
    const float* b = (const float*)d_in[1];   // memory_bank [65536,128]
    if (n_in >= 2 && in_sizes[0] > in_sizes[1]) {   // defensive ordering
        const float* tmp = q; q = b; b = tmp;
    }
    float* out = (float*)d_out;

    static uint4* p_bt = nullptr;
    static uint4* p_qt = nullptr;
    static float *p_bsq = nullptr, *p_qsq = nullptr;
    if (!p_bt) {
        cudaGetSymbolAddress((void**)&p_bt, g_bt);
        cudaGetSymbolAddress((void**)&p_qt, g_qt);
        cudaGetSymbolAddress((void**)&p_bsq, g_bsq);
        cudaGetSymbolAddress((void**)&p_qsq, g_qsq);
    }

    cudaFuncSetAttribute(knn_main_kernel,
                         cudaFuncAttributeMaxDynamicSharedMemorySize, SMEM_SZ);

    const int bchunks = N_B * 16;
    const int qchunks = M_Q * 16;
    pack_norms_kernel<<<bchunks / 256, 256>>>((const float4*)b, p_bt, p_bsq, bchunks);
    pack_norms_kernel<<<qchunks / 256, 256>>>((const float4*)q, p_qt, p_qsq, qchunks);

    dim3 grid(M_Q / MTILE, NSPLIT);
    knn_main_kernel<<<grid, THREADS, SMEM_SZ>>>();

    knn_finalize_kernel<<<M_Q / 256, 256>>>(out);
}